// round 14
// baseline (speedup 1.0000x reference)
#include <cuda_runtime.h>
#include <math.h>

typedef unsigned long long u64;

#define NV    25
#define NE    1600
#define NTHR  384
#define RSF   66              // floats per state row (33 u64)
#define PSTR  (2 * 64 * RSF)  // per-pair buffer stride (TA, TB)

// shared float offsets — weights & A stored pair-duplicated (w,w)
#define O_WT1 0               // Wd[c*128 + o*2 + {0,1}] = W[o*64+c]   (8192)
#define O_WT2 8192
#define O_WTP 16384
#define O_AT  24576           // Ad[u*64 + v*2 + {0,1}] = A^T[u][v]    (1600)
#define O_B1  26176
#define O_B2  26240
#define O_BP  26304
#define O_PE  26368           // 3 pairs x 5 rows x 64                 (960)
#define O_BUF 27328           // 3 pairs x (TA,TB)
#define SMF   (O_BUF + 3 * PSTR)    // 52672 floats
#define SMB   (SMF * 4)             // 210688 bytes

extern __shared__ float sm[];

__device__ __forceinline__ void fma2(u64& a, u64 x, u64 w) {
    asm("fma.rn.f32x2 %0,%1,%2,%0;" : "+l"(a) : "l"(x), "l"(w));
}
__device__ __forceinline__ float2 unp(u64 a) {
    float2 f; asm("mov.b64 {%0,%1},%2;" : "=f"(f.x), "=f"(f.y) : "l"(a)); return f;
}
__device__ __forceinline__ void psync(int bid) {
    asm volatile("bar.sync %0, 128;" :: "r"(bid) : "memory");
}

// W mainloop: acc[i][k] = sum_c W[o0+i][c] * x[c][jq+16k]
// packed weights loaded directly (no register packing)
__device__ __forceinline__ void mmW(int wofs, int src, int jq, int o0, u64 acc[8][2])
{
#pragma unroll
    for (int i = 0; i < 8; i++) { acc[i][0] = 0ULL; acc[i][1] = 0ULL; }
#pragma unroll 8
    for (int c = 0; c < 64; c++) {
        const float* xr = sm + src + c * RSF + jq * 2;
        const u64 x0 = *(const u64*)(xr);
        const u64 x1 = *(const u64*)(xr + 32);
        const float* wr = sm + wofs + c * 128 + o0 * 2;
        const ulonglong2 w0 = *(const ulonglong2*)(wr);
        const ulonglong2 w1 = *(const ulonglong2*)(wr + 4);
        const ulonglong2 w2 = *(const ulonglong2*)(wr + 8);
        const ulonglong2 w3 = *(const ulonglong2*)(wr + 12);
        const u64 wp[8] = {w0.x, w0.y, w1.x, w1.y, w2.x, w2.y, w3.x, w3.y};
#pragma unroll
        for (int i = 0; i < 8; i++) {
            fma2(acc[i][0], x0, wp[i]);
            fma2(acc[i][1], x1, wp[i]);
        }
    }
}

// A matmul: dst[c][v] = sum_u At[u][v] * src[c][u]
__device__ __forceinline__ void amat(int src, int dst, int cq, int vb)
{
    u64 acc[2][8];
#pragma unroll
    for (int ci = 0; ci < 2; ci++)
#pragma unroll
        for (int m = 0; m < 8; m++) acc[ci][m] = 0ULL;
#pragma unroll 5
    for (int u = 0; u < NV; u++) {
        const u64 x0 = *(const u64*)(sm + src + cq * RSF + u * 2);
        const u64 x1 = *(const u64*)(sm + src + (cq + 32) * RSF + u * 2);
        const float* ar = sm + O_AT + u * 64 + vb * 2;
        const ulonglong2 a0 = *(const ulonglong2*)(ar);
        const ulonglong2 a1 = *(const ulonglong2*)(ar + 4);
        const ulonglong2 a2 = *(const ulonglong2*)(ar + 8);
        const ulonglong2 a3 = *(const ulonglong2*)(ar + 12);
        const u64 ap[8] = {a0.x, a0.y, a1.x, a1.y, a2.x, a2.y, a3.x, a3.y};
#pragma unroll
        for (int m = 0; m < 8; m++) {
            fma2(acc[0][m], x0, ap[m]);
            fma2(acc[1][m], x1, ap[m]);
        }
    }
#pragma unroll
    for (int ci = 0; ci < 2; ci++) {
        float* dr = sm + dst + (cq + 32 * ci) * RSF + vb * 2;
#pragma unroll
        for (int m = 0; m < 8; m++)
            *(u64*)(dr + m * 2) = acc[ci][m];
    }
}

// W stage with bias + leaky relu: TA -> TB
__device__ __forceinline__ void wact(int wofs, int bofs, int taB, int tbB,
                                     int jq, int o0)
{
    u64 acc[8][2];
    mmW(wofs, taB, jq, o0, acc);
#pragma unroll
    for (int i = 0; i < 8; i++) {
        const float b = sm[bofs + o0 + i];
        float* dr = sm + tbB + (o0 + i) * RSF + jq * 2;
#pragma unroll
        for (int k = 0; k < 2; k++) {
            float2 r = unp(acc[i][k]);
            r.x += b; r.y += b;
            r.x = fmaxf(r.x, 0.01f * r.x);
            r.y = fmaxf(r.y, 0.01f * r.y);
            *(float2*)(dr + 32 * k) = r;
        }
    }
}

// (A, W1+relu, A, W2+relu): TB -> TB, pair-scoped barriers
__device__ __forceinline__ void core(int taB, int tbB, int cq, int vb,
                                     int jq, int o0, int bid)
{
    amat(tbB, taB, cq, vb);              psync(bid);
    wact(O_WT1, O_B1, taB, tbB, jq, o0); psync(bid);
    amat(tbB, taB, cq, vb);              psync(bid);
    wact(O_WT2, O_B2, taB, tbB, jq, o0); psync(bid);
}

__global__ void __launch_bounds__(NTHR, 1)
sode_kernel(const float* __restrict__ gfp, const float* __restrict__ gts,
            const float* __restrict__ gA,
            const float* __restrict__ gW1, const float* __restrict__ gb1,
            const float* __restrict__ gW2, const float* __restrict__ gb2,
            const float* __restrict__ gWp, const float* __restrict__ gbp,
            const float* __restrict__ gpe,
            float* __restrict__ out, int nb)
{
    const int tid  = threadIdx.x;
    const int pr   = tid >> 7;            // pair 0..2
    const int ltid = tid & 127;
    const int bid  = pr + 1;              // named barrier id
    const int n0   = blockIdx.x * 6 + pr * 2;
    const bool act = (n0 < nb);
    const int tt0  = n0 & 63;
    const int jq   = ltid & 15, o0 = (ltid >> 4) << 3;
    const int cq   = ltid & 31, vb = ((ltid >> 5) & 3) << 3;

    const int taB = O_BUF + pr * PSTR;
    const int tbB = taB + 64 * RSF;
    const int peB = O_PE + pr * 320;

    // ---- shared init: weights transposed + pair-duplicated ----
    for (int i = tid; i < 4096; i += NTHR) {
        const int c = i >> 6, o = i & 63;
        const int d = c * 128 + o * 2;
        float w;
        w = gW1[o * 64 + c]; sm[O_WT1 + d] = w; sm[O_WT1 + d + 1] = w;
        w = gW2[o * 64 + c]; sm[O_WT2 + d] = w; sm[O_WT2 + d + 1] = w;
        w = gWp[o * 64 + c]; sm[O_WTP + d] = w; sm[O_WTP + d + 1] = w;
    }
    for (int i = tid; i < 800; i += NTHR) {
        const int u = i >> 5, v = i & 31;
        const float a = (v < NV) ? gA[v * NV + u] : 0.f;
        sm[O_AT + u * 64 + v * 2]     = a;
        sm[O_AT + u * 64 + v * 2 + 1] = a;
    }
    if (tid < 64) {
        sm[O_B1 + tid] = gb1[tid];
        sm[O_B2 + tid] = gb2[tid];
        sm[O_BP + tid] = gbp[tid];
    }
    for (int i = ltid; i < 320; i += 128)
        sm[peB + i] = act ? gpe[tt0 * 64 + i] : 0.f;

    // ---- Y state in registers; load first_point, emit out[0] ----
    float2 Yr[8][2];
#pragma unroll
    for (int i = 0; i < 8; i++) {
        const int o = o0 + i;
#pragma unroll
        for (int k = 0; k < 2; k++) {
            const int v = jq + 16 * k;
            float2 Yv = make_float2(0.f, 0.f);
            if (act && v < NV) {
                Yv.x = gfp[(size_t)n0 * NE + o * NV + v];
                Yv.y = gfp[(size_t)(n0 + 1) * NE + o * NV + v];
                out[(size_t)n0 * NE + o * NV + v]       = Yv.x;
                out[(size_t)(n0 + 1) * NE + o * NV + v] = Yv.y;
            }
            Yr[i][k] = Yv;
        }
    }
    __syncthreads();

    float2 k1[8][2], k2[8][2];

#pragma unroll 1
    for (int st = 0; st < 3; st++) {
        const float t0 = gts[st];
        const float dt = gts[st + 1] - t0;
        const int r1 = (int)floorf(t0);
        const int r2 = (int)floorf(t0 + dt * (1.f / 3.f));
        const int r3 = (int)floorf(t0 + dt * (2.f / 3.f));
        const int r4 = (int)floorf(t0 + dt);

        // prep1: TB = Yr + pe(r1)
#pragma unroll
        for (int i = 0; i < 8; i++) {
            const int o = o0 + i;
            const float px = sm[peB + r1 * 64 + o];
            const float py = sm[peB + (r1 + 1) * 64 + o];
            float* tr = sm + tbB + o * RSF + jq * 2;
#pragma unroll
            for (int k = 0; k < 2; k++) {
                float2 tb;
                tb.x = Yr[i][k].x + px;
                tb.y = Yr[i][k].y + py;
                *(float2*)(tr + 32 * k) = tb;
            }
        }
        psync(bid);

        // ---- eval 1: k1 (regs); TB <- Yr + dt/3*k1 + pe(r2) ----
        core(taB, tbB, cq, vb, jq, o0, bid);
        {
            u64 acc[8][2];
            mmW(O_WTP, tbB, jq, o0, acc);
            psync(bid);
            const float f = dt * (1.f / 3.f);
#pragma unroll
            for (int i = 0; i < 8; i++) {
                const int o = o0 + i;
                const float b = sm[O_BP + o];
                const float px = sm[peB + r2 * 64 + o];
                const float py = sm[peB + (r2 + 1) * 64 + o];
                float* tr = sm + tbB + o * RSF + jq * 2;
#pragma unroll
                for (int k = 0; k < 2; k++) {
                    float2 v = unp(acc[i][k]);
                    v.x += b; v.y += b;
                    k1[i][k] = v;
                    float2 tb;
                    tb.x = Yr[i][k].x + f * v.x + px;
                    tb.y = Yr[i][k].y + f * v.y + py;
                    *(float2*)(tr + 32 * k) = tb;
                }
            }
            psync(bid);
        }

        // ---- eval 2: k2 (regs); TB <- Yr + dt*k2 - dt/3*k1 + pe(r3) ----
        core(taB, tbB, cq, vb, jq, o0, bid);
        {
            u64 acc[8][2];
            mmW(O_WTP, tbB, jq, o0, acc);
            psync(bid);
            const float f3 = dt * (1.f / 3.f);
#pragma unroll
            for (int i = 0; i < 8; i++) {
                const int o = o0 + i;
                const float b = sm[O_BP + o];
                const float px = sm[peB + r3 * 64 + o];
                const float py = sm[peB + (r3 + 1) * 64 + o];
                float* tr = sm + tbB + o * RSF + jq * 2;
#pragma unroll
                for (int k = 0; k < 2; k++) {
                    float2 v = unp(acc[i][k]);
                    v.x += b; v.y += b;
                    k2[i][k] = v;
                    float2 tb;
                    tb.x = Yr[i][k].x + dt * v.x - f3 * k1[i][k].x + px;
                    tb.y = Yr[i][k].y + dt * v.y - f3 * k1[i][k].y + py;
                    *(float2*)(tr + 32 * k) = tb;
                }
            }
            psync(bid);
        }

        // ---- eval 3: k3; TB <- Yr + dt*(k1-k2+k3) + pe(r4);
        //      k2 <- k1 + 3*(k2+k3) ----
        core(taB, tbB, cq, vb, jq, o0, bid);
        {
            u64 acc[8][2];
            mmW(O_WTP, tbB, jq, o0, acc);
            psync(bid);
#pragma unroll
            for (int i = 0; i < 8; i++) {
                const int o = o0 + i;
                const float b = sm[O_BP + o];
                const float px = sm[peB + r4 * 64 + o];
                const float py = sm[peB + (r4 + 1) * 64 + o];
                float* tr = sm + tbB + o * RSF + jq * 2;
#pragma unroll
                for (int k = 0; k < 2; k++) {
                    float2 k3 = unp(acc[i][k]);
                    k3.x += b; k3.y += b;
                    const float2 K1 = k1[i][k], K2 = k2[i][k];
                    float2 tb, kn;
                    tb.x = Yr[i][k].x + dt * (K1.x - K2.x + k3.x) + px;
                    tb.y = Yr[i][k].y + dt * (K1.y - K2.y + k3.y) + py;
                    kn.x = K1.x + 3.f * (K2.x + k3.x);
                    kn.y = K1.y + 3.f * (K2.y + k3.y);
                    k2[i][k] = kn;
                    *(float2*)(tr + 32 * k) = tb;
                }
            }
            psync(bid);
        }

        // ---- eval 4: k4; Yr += dt/8*(k2 + k4); emit out[st+1] ----
        core(taB, tbB, cq, vb, jq, o0, bid);
        {
            u64 acc[8][2];
            mmW(O_WTP, tbB, jq, o0, acc);
            float* ob = out + (size_t)(st + 1) * nb * NE + (size_t)n0 * NE;
            const float f = dt * 0.125f;
#pragma unroll
            for (int i = 0; i < 8; i++) {
                const int o = o0 + i;
                const float b = sm[O_BP + o];
#pragma unroll
                for (int k = 0; k < 2; k++) {
                    const int v = jq + 16 * k;
                    float2 k4 = unp(acc[i][k]);
                    k4.x += b; k4.y += b;
                    const float2 K2 = k2[i][k];
                    float2 Yv = Yr[i][k];
                    Yv.x += f * (K2.x + k4.x);
                    Yv.y += f * (K2.y + k4.y);
                    Yr[i][k] = Yv;
                    if (act && v < NV) {
                        ob[o * NV + v]      = Yv.x;
                        ob[NE + o * NV + v] = Yv.y;
                    }
                }
            }
            psync(bid);   // TB consumed before next prep overwrites
        }
    }
}

extern "C" void kernel_launch(void* const* d_in, const int* in_sizes, int n_in,
                              void* d_out, int out_size)
{
    const float* fp = (const float*)d_in[0];
    const float* ts = (const float*)d_in[1];
    const float* A  = (const float*)d_in[2];
    const float* W1 = (const float*)d_in[3];
    const float* b1 = (const float*)d_in[4];
    const float* W2 = (const float*)d_in[5];
    const float* b2 = (const float*)d_in[6];
    const float* Wp = (const float*)d_in[7];
    const float* bp = (const float*)d_in[8];
    const float* pe = (const float*)d_in[9];
    float* out = (float*)d_out;

    const int nb = in_sizes[0] / NE;
    const int grid = (nb + 5) / 6;

    cudaFuncSetAttribute(sode_kernel,
                         cudaFuncAttributeMaxDynamicSharedMemorySize, SMB);
    sode_kernel<<<grid, NTHR, SMB>>>(fp, ts, A, W1, b1, W2, b2, Wp, bp, pe,
                                     out, nb);
}

// round 15
// speedup vs baseline: 1.2870x; 1.2870x over previous
#include <cuda_runtime.h>
#include <math.h>

typedef unsigned long long u64;

#define NV    25
#define NE    1600
#define NTHR  384
#define RSF   66              // floats per state row (33 u64)
#define PSTR  (2 * 64 * RSF)  // per-pair buffer stride (b0, b1)

// shared float offsets
#define O_WT1 0               // Wt[c*64+o] = W[o*64+c]      (4096)
#define O_WT2 4096
#define O_WTP 8192
#define O_AT  12288           // scalar A^T: [u*32+v], pad   (800)
#define O_B1  13088
#define O_B2  13152
#define O_BP  13216
#define O_PE  13280           // 3 pairs x 5 rows x 64       (960)
#define O_BUF 14240           // 3 pairs x (b0,b1)
#define SMF   (O_BUF + 3 * PSTR)    // 39584 floats
#define SMB   (SMF * 4)             // 158336 bytes

extern __shared__ float sm[];

__device__ __forceinline__ u64 pack2(float x) {
    u64 r; asm("mov.b64 %0,{%1,%1};" : "=l"(r) : "f"(x)); return r;
}
__device__ __forceinline__ void fma2(u64& a, u64 x, u64 w) {
    asm("fma.rn.f32x2 %0,%1,%2,%0;" : "+l"(a) : "l"(x), "l"(w));
}
__device__ __forceinline__ float2 unp(u64 a) {
    float2 f; asm("mov.b64 {%0,%1},%2;" : "=f"(f.x), "=f"(f.y) : "l"(a)); return f;
}
__device__ __forceinline__ void psync(int bid) {
    asm volatile("bar.sync %0, 128;" :: "r"(bid) : "memory");
}

// W mainloop: acc[i][k] = sum_c W[o0+i][c] * x[c][jq+16k]
__device__ __forceinline__ void mmW(int wofs, int src, int jq, int o0, u64 acc[8][2])
{
#pragma unroll
    for (int i = 0; i < 8; i++) { acc[i][0] = 0ULL; acc[i][1] = 0ULL; }
#pragma unroll 8
    for (int c = 0; c < 64; c++) {
        const float* xr = sm + src + c * RSF + jq * 2;
        const u64 x0 = *(const u64*)(xr);
        const u64 x1 = *(const u64*)(xr + 32);
        const float4 wa = *(const float4*)(sm + wofs + c * 64 + o0);
        const float4 wb = *(const float4*)(sm + wofs + c * 64 + o0 + 4);
        const float wv[8] = {wa.x, wa.y, wa.z, wa.w, wb.x, wb.y, wb.z, wb.w};
#pragma unroll
        for (int i = 0; i < 8; i++) {
            const u64 wp = pack2(wv[i]);
            fma2(acc[i][0], x0, wp);
            fma2(acc[i][1], x1, wp);
        }
    }
}

// A matmul: dst[c][v] = sum_u At[u][v] * src[c][u]
__device__ __forceinline__ void amat(int src, int dst, int cq, int vb)
{
    u64 acc[2][8];
#pragma unroll
    for (int ci = 0; ci < 2; ci++)
#pragma unroll
        for (int m = 0; m < 8; m++) acc[ci][m] = 0ULL;
#pragma unroll 5
    for (int u = 0; u < NV; u++) {
        const u64 x0 = *(const u64*)(sm + src + cq * RSF + u * 2);
        const u64 x1 = *(const u64*)(sm + src + (cq + 32) * RSF + u * 2);
        const float4 aa = *(const float4*)(sm + O_AT + u * 32 + vb);
        const float4 ab = *(const float4*)(sm + O_AT + u * 32 + vb + 4);
        const float av[8] = {aa.x, aa.y, aa.z, aa.w, ab.x, ab.y, ab.z, ab.w};
#pragma unroll
        for (int m = 0; m < 8; m++) {
            const u64 ap = pack2(av[m]);
            fma2(acc[0][m], x0, ap);
            fma2(acc[1][m], x1, ap);
        }
    }
#pragma unroll
    for (int ci = 0; ci < 2; ci++) {
        float* dr = sm + dst + (cq + 32 * ci) * RSF + vb * 2;
#pragma unroll
        for (int m = 0; m < 8; m++)
            *(u64*)(dr + m * 2) = acc[ci][m];
    }
}

// W stage with bias + leaky relu: src -> dst
__device__ __forceinline__ void wact(int wofs, int bofs, int src, int dst,
                                     int jq, int o0)
{
    u64 acc[8][2];
    mmW(wofs, src, jq, o0, acc);
#pragma unroll
    for (int i = 0; i < 8; i++) {
        const float b = sm[bofs + o0 + i];
        float* dr = sm + dst + (o0 + i) * RSF + jq * 2;
#pragma unroll
        for (int k = 0; k < 2; k++) {
            float2 r = unp(acc[i][k]);
            r.x += b; r.y += b;
            r.x = fmaxf(r.x, 0.01f * r.x);
            r.y = fmaxf(r.y, 0.01f * r.y);
            *(float2*)(dr + 32 * k) = r;
        }
    }
}

// (A, W1+relu, A, W2+relu): arg X -> X, scratch Z; then mmWp(X) by caller
__device__ __forceinline__ void core(int X, int Z, int cq, int vb,
                                     int jq, int o0, int bid)
{
    amat(X, Z, cq, vb);              psync(bid);
    wact(O_WT1, O_B1, Z, X, jq, o0); psync(bid);
    amat(X, Z, cq, vb);              psync(bid);
    wact(O_WT2, O_B2, Z, X, jq, o0); psync(bid);
}

__global__ void __launch_bounds__(NTHR, 1)
sode_kernel(const float* __restrict__ gfp, const float* __restrict__ gts,
            const float* __restrict__ gA,
            const float* __restrict__ gW1, const float* __restrict__ gb1,
            const float* __restrict__ gW2, const float* __restrict__ gb2,
            const float* __restrict__ gWp, const float* __restrict__ gbp,
            const float* __restrict__ gpe,
            float* __restrict__ out, int nb)
{
    const int tid  = threadIdx.x;
    const int pr   = tid >> 7;            // pair 0..2
    const int ltid = tid & 127;
    const int bid  = pr + 1;              // named barrier id
    const int n0   = blockIdx.x * 6 + pr * 2;
    const bool act = (n0 < nb);
    const int tt0  = n0 & 63;
    const int jq   = ltid & 15, o0 = (ltid >> 4) << 3;
    const int cq   = ltid & 31, vb = ((ltid >> 5) & 3) << 3;

    const int b0  = O_BUF + pr * PSTR;
    const int b1  = b0 + 64 * RSF;
    const int peB = O_PE + pr * 320;

    // ---- shared init (whole block) ----
    for (int i = tid; i < 4096; i += NTHR) {
        const int c = i >> 6, o = i & 63;
        sm[O_WT1 + i] = gW1[o * 64 + c];
        sm[O_WT2 + i] = gW2[o * 64 + c];
        sm[O_WTP + i] = gWp[o * 64 + c];
    }
    for (int i = tid; i < 800; i += NTHR) {
        const int u = i >> 5, v = i & 31;
        sm[O_AT + i] = (v < NV) ? gA[v * NV + u] : 0.f;
    }
    if (tid < 64) {
        sm[O_B1 + tid] = gb1[tid];
        sm[O_B2 + tid] = gb2[tid];
        sm[O_BP + tid] = gbp[tid];
    }
    for (int i = ltid; i < 320; i += 128)
        sm[peB + i] = act ? gpe[tt0 * 64 + i] : 0.f;

    // ---- Y state in registers; load first_point, emit out[0] ----
    float2 Yr[8][2];
#pragma unroll
    for (int i = 0; i < 8; i++) {
        const int o = o0 + i;
#pragma unroll
        for (int k = 0; k < 2; k++) {
            const int v = jq + 16 * k;
            float2 Yv = make_float2(0.f, 0.f);
            if (act && v < NV) {
                Yv.x = gfp[(size_t)n0 * NE + o * NV + v];
                Yv.y = gfp[(size_t)(n0 + 1) * NE + o * NV + v];
                out[(size_t)n0 * NE + o * NV + v]       = Yv.x;
                out[(size_t)(n0 + 1) * NE + o * NV + v] = Yv.y;
            }
            Yr[i][k] = Yv;
        }
    }
    __syncthreads();

    float2 k1[8][2], k2[8][2];

    // prep for step 0 eval 1: b0 = Yr + pe(r1=0)
    {
#pragma unroll
        for (int i = 0; i < 8; i++) {
            const int o = o0 + i;
            const float px = sm[peB + o];          // row 0
            const float py = sm[peB + 64 + o];     // row 1
            float* tr = sm + b0 + o * RSF + jq * 2;
#pragma unroll
            for (int k = 0; k < 2; k++) {
                float2 tb;
                tb.x = Yr[i][k].x + px;
                tb.y = Yr[i][k].y + py;
                *(float2*)(tr + 32 * k) = tb;
            }
        }
        psync(bid);
    }

#pragma unroll 1
    for (int st = 0; st < 3; st++) {
        const float t0 = gts[st];
        const float dt = gts[st + 1] - t0;
        const int r2 = (int)floorf(t0 + dt * (1.f / 3.f));
        const int r3 = (int)floorf(t0 + dt * (2.f / 3.f));
        const int r4 = (int)floorf(t0 + dt);
        const int rn = (int)floorf(gts[st + 1]);   // next step's r1 (== r4)

        // ---- eval 1 (arg b0, scratch b1): k1; b1 <- Yr + dt/3*k1 + pe(r2)
        core(b0, b1, cq, vb, jq, o0, bid);
        {
            u64 acc[8][2];
            mmW(O_WTP, b0, jq, o0, acc);
            const float f = dt * (1.f / 3.f);
#pragma unroll
            for (int i = 0; i < 8; i++) {
                const int o = o0 + i;
                const float b = sm[O_BP + o];
                const float px = sm[peB + r2 * 64 + o];
                const float py = sm[peB + (r2 + 1) * 64 + o];
                float* tr = sm + b1 + o * RSF + jq * 2;
#pragma unroll
                for (int k = 0; k < 2; k++) {
                    float2 v = unp(acc[i][k]);
                    v.x += b; v.y += b;
                    k1[i][k] = v;
                    float2 tb;
                    tb.x = Yr[i][k].x + f * v.x + px;
                    tb.y = Yr[i][k].y + f * v.y + py;
                    *(float2*)(tr + 32 * k) = tb;
                }
            }
            psync(bid);
        }

        // ---- eval 2 (arg b1, scratch b0): k2; b0 <- Yr + dt*k2 - dt/3*k1 + pe(r3)
        core(b1, b0, cq, vb, jq, o0, bid);
        {
            u64 acc[8][2];
            mmW(O_WTP, b1, jq, o0, acc);
            const float f3 = dt * (1.f / 3.f);
#pragma unroll
            for (int i = 0; i < 8; i++) {
                const int o = o0 + i;
                const float b = sm[O_BP + o];
                const float px = sm[peB + r3 * 64 + o];
                const float py = sm[peB + (r3 + 1) * 64 + o];
                float* tr = sm + b0 + o * RSF + jq * 2;
#pragma unroll
                for (int k = 0; k < 2; k++) {
                    float2 v = unp(acc[i][k]);
                    v.x += b; v.y += b;
                    k2[i][k] = v;
                    float2 tb;
                    tb.x = Yr[i][k].x + dt * v.x - f3 * k1[i][k].x + px;
                    tb.y = Yr[i][k].y + dt * v.y - f3 * k1[i][k].y + py;
                    *(float2*)(tr + 32 * k) = tb;
                }
            }
            psync(bid);
        }

        // ---- eval 3 (arg b0, scratch b1): k3; b1 <- Yr + dt*(k1-k2+k3) + pe(r4);
        //      k2 <- k1 + 3*(k2+k3)
        core(b0, b1, cq, vb, jq, o0, bid);
        {
            u64 acc[8][2];
            mmW(O_WTP, b0, jq, o0, acc);
#pragma unroll
            for (int i = 0; i < 8; i++) {
                const int o = o0 + i;
                const float b = sm[O_BP + o];
                const float px = sm[peB + r4 * 64 + o];
                const float py = sm[peB + (r4 + 1) * 64 + o];
                float* tr = sm + b1 + o * RSF + jq * 2;
#pragma unroll
                for (int k = 0; k < 2; k++) {
                    float2 k3 = unp(acc[i][k]);
                    k3.x += b; k3.y += b;
                    const float2 K1 = k1[i][k], K2 = k2[i][k];
                    float2 tb, kn;
                    tb.x = Yr[i][k].x + dt * (K1.x - K2.x + k3.x) + px;
                    tb.y = Yr[i][k].y + dt * (K1.y - K2.y + k3.y) + py;
                    kn.x = K1.x + 3.f * (K2.x + k3.x);
                    kn.y = K1.y + 3.f * (K2.y + k3.y);
                    k2[i][k] = kn;
                    *(float2*)(tr + 32 * k) = tb;
                }
            }
            psync(bid);
        }

        // ---- eval 4 (arg b1, scratch b0): k4; Yr += dt/8*(k2 + k4);
        //      emit out[st+1]; fused prep: b0 <- Yrnew + pe(rn)
        core(b1, b0, cq, vb, jq, o0, bid);
        {
            u64 acc[8][2];
            mmW(O_WTP, b1, jq, o0, acc);
            float* ob = out + (size_t)(st + 1) * nb * NE + (size_t)n0 * NE;
            const float f = dt * 0.125f;
#pragma unroll
            for (int i = 0; i < 8; i++) {
                const int o = o0 + i;
                const float b = sm[O_BP + o];
                const float px = sm[peB + rn * 64 + o];
                const float py = sm[peB + (rn + 1) * 64 + o];
                float* tr = sm + b0 + o * RSF + jq * 2;
#pragma unroll
                for (int k = 0; k < 2; k++) {
                    const int v = jq + 16 * k;
                    float2 k4 = unp(acc[i][k]);
                    k4.x += b; k4.y += b;
                    const float2 K2 = k2[i][k];
                    float2 Yv = Yr[i][k];
                    Yv.x += f * (K2.x + k4.x);
                    Yv.y += f * (K2.y + k4.y);
                    Yr[i][k] = Yv;
                    if (act && v < NV) {
                        ob[o * NV + v]      = Yv.x;
                        ob[NE + o * NV + v] = Yv.y;
                    }
                    float2 tb;
                    tb.x = Yv.x + px;
                    tb.y = Yv.y + py;
                    *(float2*)(tr + 32 * k) = tb;
                }
            }
            psync(bid);
        }
    }
}

extern "C" void kernel_launch(void* const* d_in, const int* in_sizes, int n_in,
                              void* d_out, int out_size)
{
    const float* fp = (const float*)d_in[0];
    const float* ts = (const float*)d_in[1];
    const float* A  = (const float*)d_in[2];
    const float* W1 = (const float*)d_in[3];
    const float* b1 = (const float*)d_in[4];
    const float* W2 = (const float*)d_in[5];
    const float* b2 = (const float*)d_in[6];
    const float* Wp = (const float*)d_in[7];
    const float* bp = (const float*)d_in[8];
    const float* pe = (const float*)d_in[9];
    float* out = (float*)d_out;

    const int nb = in_sizes[0] / NE;
    const int grid = (nb + 5) / 6;

    cudaFuncSetAttribute(sode_kernel,
                         cudaFuncAttributeMaxDynamicSharedMemorySize, SMB);
    sode_kernel<<<grid, NTHR, SMB>>>(fp, ts, A, W1, b1, W2, b2, Wp, bp, pe,
                                     out, nb);
}